// round 9
// baseline (speedup 1.0000x reference)
#include <cuda_runtime.h>
#include <cuda_bf16.h>
#include <mma.h>
#include <math.h>

using namespace nvcuda;

#define N 16384
#define HID 256
#define MI 128
#define NEDGE (N*4)

// stats layout inside g_stats
#define RS1 0
#define RS2 (N)
#define PS1 (2*N)
#define PS2 (3*N)
#define SP1 (4*N)
#define SP2 (5*N)

// ---------------- scratch (device globals; no allocation allowed) ----------
__device__ float g_p1[(size_t)N*MI];
__device__ float g_p2[(size_t)N*MI];
__device__ __nv_bfloat16 g_p1h[(size_t)N*MI];
__device__ __nv_bfloat16 g_p2h[(size_t)N*MI];
__device__ float g_stats[6*N];

// ---------------- nop spacer (positions sim as the 4th launch for ncu) -----
__global__ void nop_kernel() {}

// ============ projection (tf32 wmma): p = l2norm(relu(h@W + b)) =============
// CTA: 16 rows x 128 cols, 128 threads = 4 warps; warp w owns col range w*32.
// First 384 blocks also zero g_stats (256 floats each; 384*256 = 6*N).
#define PJ_LD 132

__global__ void __launch_bounds__(128, 1) proj_kernel(
        const float* __restrict__ h1, const float* __restrict__ h2,
        const float* __restrict__ W, const float* __restrict__ bias) {
    __shared__ float cs[16 * PJ_LD];
    __shared__ float rowsq[16];

    int tid = threadIdx.x;
    int warp = tid >> 5;
    int row0 = blockIdx.x * 16;

    if (blockIdx.x < 384) {
        int base = blockIdx.x * 256;
        g_stats[base + tid] = 0.0f;
        g_stats[base + tid + 128] = 0.0f;
    }

    const float* hsrc;
    float* pdst;
    __nv_bfloat16* phdst;
    if (row0 < N) {
        hsrc = h1 + (size_t)row0 * HID;
        pdst = g_p1 + (size_t)row0 * MI;
        phdst = g_p1h + (size_t)row0 * MI;
    } else {
        int r0 = row0 - N;
        hsrc = h2 + (size_t)r0 * HID;
        pdst = g_p2 + (size_t)r0 * MI;
        phdst = g_p2h + (size_t)r0 * MI;
    }

    wmma::fragment<wmma::accumulator, 16, 16, 8, float> acc0;
    wmma::fragment<wmma::accumulator, 16, 16, 8, float> acc1;
    wmma::fill_fragment(acc0, 0.0f);
    wmma::fill_fragment(acc1, 0.0f);

    int n0 = warp * 32;
    for (int k = 0; k < HID; k += 8) {
        wmma::fragment<wmma::matrix_a, 16, 16, 8, wmma::precision::tf32,
                       wmma::row_major> af;
        wmma::load_matrix_sync(af, hsrc + k, HID);
        for (int i = 0; i < af.num_elements; i++)
            af.x[i] = wmma::__float_to_tf32(af.x[i]);

        wmma::fragment<wmma::matrix_b, 16, 16, 8, wmma::precision::tf32,
                       wmma::row_major> bf0;
        wmma::fragment<wmma::matrix_b, 16, 16, 8, wmma::precision::tf32,
                       wmma::row_major> bf1;
        wmma::load_matrix_sync(bf0, W + (size_t)k * MI + n0, MI);
        wmma::load_matrix_sync(bf1, W + (size_t)k * MI + n0 + 16, MI);
        for (int i = 0; i < bf0.num_elements; i++)
            bf0.x[i] = wmma::__float_to_tf32(bf0.x[i]);
        for (int i = 0; i < bf1.num_elements; i++)
            bf1.x[i] = wmma::__float_to_tf32(bf1.x[i]);

        wmma::mma_sync(acc0, af, bf0, acc0);
        wmma::mma_sync(acc1, af, bf1, acc1);
    }

    wmma::store_matrix_sync(cs + n0, acc0, PJ_LD, wmma::mem_row_major);
    wmma::store_matrix_sync(cs + n0 + 16, acc1, PJ_LD, wmma::mem_row_major);
    if (tid < 16) rowsq[tid] = 0.0f;
    __syncthreads();

    int r = tid >> 3;
    int c0 = (tid & 7) * 16;
    float vals[16];
    float sq = 0.0f;
    for (int c = 0; c < 16; c++) {
        float v = cs[r * PJ_LD + c0 + c] + bias[c0 + c];
        v = fmaxf(v, 0.0f);
        vals[c] = v;
        sq += v * v;
    }
    atomicAdd(&rowsq[r], sq);
    __syncthreads();

    float s = rsqrtf(rowsq[r]);
    for (int c = 0; c < 16; c++) {
        float o = vals[c] * s;
        pdst[(size_t)r * MI + c0 + c] = o;
        phdst[(size_t)r * MI + c0 + c] = __float2bfloat16_rn(o);
    }
}

// ============ sim kernel (bf16 wmma): exp(dot/T) row + col sums =============
// CTA: 256 threads = 8 warps (4M x 2N); warp tile 32x64; 128x128 CTA tile,
// K=128 resident. Pure register epilogue (accumulator lane mapping verified
// by the Round-7 runtime probe on this chip/compiler):
//   x[e] -> row = (lane>>2) + ((e>>1)&1)*8
//           col = (lane&3)*2 + (e&1) + ((e>>2)&1)*8
#define SLD 136            // A/B smem row stride in bf16 elements
#define SIM_SMEM (2*128*SLD*2)   // 69632 bytes

__global__ void __launch_bounds__(256, 2) sim_kernel() {
    extern __shared__ unsigned char dynsm[];
    __nv_bfloat16* As = (__nv_bfloat16*)dynsm;
    __nv_bfloat16* Bs = As + 128 * SLD;
    __shared__ float rowred[128];
    __shared__ float colred[128];

    int tid = threadIdx.x;
    int warp = tid >> 5;
    int lane = tid & 31;
    int wm = warp >> 1;          // 0..3  (rows wm*32)
    int wn = warp & 1;           // 0..1  (cols wn*64)
    int i0 = blockIdx.y * 128;
    int j0 = blockIdx.x * 128;

    const uint4* srcA = (const uint4*)(g_p1h + (size_t)i0 * MI);
    const uint4* srcB = (const uint4*)(g_p2h + (size_t)j0 * MI);
    for (int idx = tid; idx < 2048; idx += 256) {
        int r = idx >> 4;
        int ch = idx & 15;
        *(uint4*)(As + r * SLD + ch * 8) = srcA[idx];
        *(uint4*)(Bs + r * SLD + ch * 8) = srcB[idx];
    }
    if (tid < 128) {
        rowred[tid] = 0.0f;
        colred[tid] = 0.0f;
    }
    __syncthreads();

    wmma::fragment<wmma::accumulator, 16, 16, 16, float> acc[2][4];
    #pragma unroll
    for (int mt = 0; mt < 2; mt++) {
        #pragma unroll
        for (int nt = 0; nt < 4; nt++)
            wmma::fill_fragment(acc[mt][nt], 0.0f);
    }

    const __nv_bfloat16* abase = As + (wm * 32) * SLD;
    const __nv_bfloat16* bbase = Bs + (wn * 64) * SLD;

    #pragma unroll
    for (int k = 0; k < 8; k++) {
        wmma::fragment<wmma::matrix_a, 16, 16, 16, __nv_bfloat16,
                       wmma::row_major> af0;
        wmma::fragment<wmma::matrix_a, 16, 16, 16, __nv_bfloat16,
                       wmma::row_major> af1;
        wmma::load_matrix_sync(af0, abase + k * 16, SLD);
        wmma::load_matrix_sync(af1, abase + 16 * SLD + k * 16, SLD);
        #pragma unroll
        for (int nt = 0; nt < 4; nt++) {
            wmma::fragment<wmma::matrix_b, 16, 16, 16, __nv_bfloat16,
                           wmma::col_major> bf;
            wmma::load_matrix_sync(bf, bbase + nt * 16 * SLD + k * 16, SLD);
            wmma::mma_sync(acc[0][nt], af0, bf, acc[0][nt]);
            wmma::mma_sync(acc[1][nt], af1, bf, acc[1][nt]);
        }
    }

    // ---- register epilogue: exp + row/col sums via shuffles ----
    float cs0[4];
    float cs1[4];
    float cs2[4];
    float cs3[4];
    #pragma unroll
    for (int nt = 0; nt < 4; nt++) {
        cs0[nt] = 0.0f;
        cs1[nt] = 0.0f;
        cs2[nt] = 0.0f;
        cs3[nt] = 0.0f;
    }
    #pragma unroll
    for (int mt = 0; mt < 2; mt++) {
        float rlo = 0.0f;
        float rhi = 0.0f;
        #pragma unroll
        for (int nt = 0; nt < 4; nt++) {
            float e0 = __expf(2.0f * acc[mt][nt].x[0]);
            float e1 = __expf(2.0f * acc[mt][nt].x[1]);
            float e2 = __expf(2.0f * acc[mt][nt].x[2]);
            float e3 = __expf(2.0f * acc[mt][nt].x[3]);
            float e4 = __expf(2.0f * acc[mt][nt].x[4]);
            float e5 = __expf(2.0f * acc[mt][nt].x[5]);
            float e6 = __expf(2.0f * acc[mt][nt].x[6]);
            float e7 = __expf(2.0f * acc[mt][nt].x[7]);
            rlo += e0 + e1 + e4 + e5;     // row (lane>>2)
            rhi += e2 + e3 + e6 + e7;     // row (lane>>2)+8
            cs0[nt] += e0 + e2;           // col base
            cs1[nt] += e1 + e3;           // col base+1
            cs2[nt] += e4 + e6;           // col base+8
            cs3[nt] += e5 + e7;           // col base+9
        }
        rlo += __shfl_xor_sync(0xffffffffu, rlo, 1);
        rlo += __shfl_xor_sync(0xffffffffu, rlo, 2);
        rhi += __shfl_xor_sync(0xffffffffu, rhi, 1);
        rhi += __shfl_xor_sync(0xffffffffu, rhi, 2);
        if ((lane & 3) == 0) {
            int r = wm * 32 + mt * 16 + (lane >> 2);
            atomicAdd(&rowred[r], rlo);
            atomicAdd(&rowred[r + 8], rhi);
        }
    }
    #pragma unroll
    for (int nt = 0; nt < 4; nt++) {
        float v0 = cs0[nt];
        float v1 = cs1[nt];
        float v2 = cs2[nt];
        float v3 = cs3[nt];
        v0 += __shfl_xor_sync(0xffffffffu, v0, 4);
        v0 += __shfl_xor_sync(0xffffffffu, v0, 8);
        v0 += __shfl_xor_sync(0xffffffffu, v0, 16);
        v1 += __shfl_xor_sync(0xffffffffu, v1, 4);
        v1 += __shfl_xor_sync(0xffffffffu, v1, 8);
        v1 += __shfl_xor_sync(0xffffffffu, v1, 16);
        v2 += __shfl_xor_sync(0xffffffffu, v2, 4);
        v2 += __shfl_xor_sync(0xffffffffu, v2, 8);
        v2 += __shfl_xor_sync(0xffffffffu, v2, 16);
        v3 += __shfl_xor_sync(0xffffffffu, v3, 4);
        v3 += __shfl_xor_sync(0xffffffffu, v3, 8);
        v3 += __shfl_xor_sync(0xffffffffu, v3, 16);
        if (lane < 4) {
            int cb = wn * 64 + nt * 16 + lane * 2;
            atomicAdd(&colred[cb], v0);
            atomicAdd(&colred[cb + 1], v1);
            atomicAdd(&colred[cb + 8], v2);
            atomicAdd(&colred[cb + 9], v3);
        }
    }
    __syncthreads();

    if (tid < 128) {
        atomicAdd(&g_stats[RS1 + i0 + tid], rowred[tid]);
        atomicAdd(&g_stats[RS2 + j0 + tid], colred[tid]);
    }
}

// ---------------- positives: warp per edge, both directions (fp32) ---------
__global__ void pos_kernel(const int* __restrict__ pr, const int* __restrict__ pc) {
    int e = (blockIdx.x * blockDim.x + threadIdx.x) >> 5;
    int lane = threadIdx.x & 31;
    if (e >= NEDGE) return;
    int r = pr[e];
    int c = pc[e];
    const float4* p1r = (const float4*)(g_p1 + (size_t)r * MI);
    const float4* p2r = (const float4*)(g_p2 + (size_t)r * MI);
    const float4* p1c = (const float4*)(g_p1 + (size_t)c * MI);
    const float4* p2c = (const float4*)(g_p2 + (size_t)c * MI);
    float4 a1 = p1r[lane];
    float4 b2 = p2c[lane];
    float4 a2 = p2r[lane];
    float4 b1 = p1c[lane];
    float d1 = a1.x * b2.x + a1.y * b2.y + a1.z * b2.z + a1.w * b2.w;
    float d2 = a2.x * b1.x + a2.y * b1.y + a2.z * b1.z + a2.w * b1.w;
    for (int o = 16; o > 0; o >>= 1) {
        d1 += __shfl_down_sync(0xffffffffu, d1, o);
        d2 += __shfl_down_sync(0xffffffffu, d2, o);
    }
    if (lane == 0) {
        float s1 = 2.0f * d1;
        float s2 = 2.0f * d2;
        atomicAdd(&g_stats[SP1 + r], s1);
        atomicAdd(&g_stats[PS1 + r], __expf(s1));
        atomicAdd(&g_stats[SP2 + r], s2);
        atomicAdd(&g_stats[PS2 + r], __expf(s2));
    }
}

// ---------------- final loss reduction ----------------
__global__ void loss_kernel(float* out) {
    float acc = 0.f;
    const float invcnt = 0.25f;   // exactly 4 positives per row by construction
    for (int i = threadIdx.x; i < N; i += blockDim.x) {
        float per1 = g_stats[SP1 + i] * invcnt
                   - __logf(g_stats[RS1 + i] - g_stats[PS1 + i]);
        float per2 = g_stats[SP2 + i] * invcnt
                   - __logf(g_stats[RS2 + i] - g_stats[PS2 + i]);
        acc += per1 + per2;
    }
    __shared__ float red[32];
    for (int o = 16; o > 0; o >>= 1)
        acc += __shfl_down_sync(0xffffffffu, acc, o);
    if ((threadIdx.x & 31) == 0) red[threadIdx.x >> 5] = acc;
    __syncthreads();
    if (threadIdx.x == 0) {
        float t = 0.f;
        int nw = blockDim.x >> 5;
        for (int w = 0; w < nw; w++) t += red[w];
        out[0] = -0.5f * t / (float)N;
    }
}

// ---------------- launch ----------------
extern "C" void kernel_launch(void* const* d_in, const int* in_sizes, int n_in,
                              void* d_out, int out_size) {
    const float* h1 = (const float*)d_in[0];
    const float* h2 = (const float*)d_in[1];
    const float* W  = (const float*)d_in[2];
    const float* b  = (const float*)d_in[3];
    const int*   pr = (const int*)d_in[4];
    const int*   pc = (const int*)d_in[5];
    float* out = (float*)d_out;

    proj_kernel<<<(2 * N) / 16, 128>>>(h1, h2, W, b);
    pos_kernel<<<(NEDGE * 32) / 256, 256>>>(pr, pc);
    nop_kernel<<<1, 32>>>();

    cudaFuncSetAttribute(sim_kernel,
                         cudaFuncAttributeMaxDynamicSharedMemorySize, SIM_SMEM);
    dim3 simgrid(N / 128, N / 128);
    sim_kernel<<<simgrid, 256, SIM_SMEM>>>();

    loss_kernel<<<1, 1024>>>(out);
}

// round 10
// speedup vs baseline: 1.0023x; 1.0023x over previous
#include <cuda_runtime.h>
#include <cuda_bf16.h>
#include <mma.h>
#include <math.h>

using namespace nvcuda;

#define N 16384
#define HID 256
#define MI 128
#define NEDGE (N*4)

// stats layout inside g_stats
#define RS1 0
#define RS2 (N)
#define PS1 (2*N)
#define PS2 (3*N)
#define SP1 (4*N)
#define SP2 (5*N)

// ---------------- scratch (device globals; no allocation allowed) ----------
__device__ float g_p1[(size_t)N*MI];
__device__ float g_p2[(size_t)N*MI];
__device__ __nv_bfloat16 g_p1h[(size_t)N*MI];
__device__ __nv_bfloat16 g_p2h[(size_t)N*MI];
__device__ float g_stats[6*N];

// ---------------- nop spacer (positions sim as the 4th launch for ncu) -----
__global__ void nop_kernel() {}

// ============ projection (tf32 wmma): p = l2norm(relu(h@W + b)) =============
// CTA: 16 rows x 128 cols, 128 threads = 4 warps; warp w owns col range w*32.
// First 384 blocks also zero g_stats (256 floats each; 384*256 = 6*N).
#define PJ_LD 132

__global__ void __launch_bounds__(128, 1) proj_kernel(
        const float* __restrict__ h1, const float* __restrict__ h2,
        const float* __restrict__ W, const float* __restrict__ bias) {
    __shared__ float cs[16 * PJ_LD];
    __shared__ float rowsq[16];

    int tid = threadIdx.x;
    int warp = tid >> 5;
    int row0 = blockIdx.x * 16;

    if (blockIdx.x < 384) {
        int base = blockIdx.x * 256;
        g_stats[base + tid] = 0.0f;
        g_stats[base + tid + 128] = 0.0f;
    }

    const float* hsrc;
    float* pdst;
    __nv_bfloat16* phdst;
    if (row0 < N) {
        hsrc = h1 + (size_t)row0 * HID;
        pdst = g_p1 + (size_t)row0 * MI;
        phdst = g_p1h + (size_t)row0 * MI;
    } else {
        int r0 = row0 - N;
        hsrc = h2 + (size_t)r0 * HID;
        pdst = g_p2 + (size_t)r0 * MI;
        phdst = g_p2h + (size_t)r0 * MI;
    }

    wmma::fragment<wmma::accumulator, 16, 16, 8, float> acc0;
    wmma::fragment<wmma::accumulator, 16, 16, 8, float> acc1;
    wmma::fill_fragment(acc0, 0.0f);
    wmma::fill_fragment(acc1, 0.0f);

    int n0 = warp * 32;
    for (int k = 0; k < HID; k += 8) {
        wmma::fragment<wmma::matrix_a, 16, 16, 8, wmma::precision::tf32,
                       wmma::row_major> af;
        wmma::load_matrix_sync(af, hsrc + k, HID);
        for (int i = 0; i < af.num_elements; i++)
            af.x[i] = wmma::__float_to_tf32(af.x[i]);

        wmma::fragment<wmma::matrix_b, 16, 16, 8, wmma::precision::tf32,
                       wmma::row_major> bf0;
        wmma::fragment<wmma::matrix_b, 16, 16, 8, wmma::precision::tf32,
                       wmma::row_major> bf1;
        wmma::load_matrix_sync(bf0, W + (size_t)k * MI + n0, MI);
        wmma::load_matrix_sync(bf1, W + (size_t)k * MI + n0 + 16, MI);
        for (int i = 0; i < bf0.num_elements; i++)
            bf0.x[i] = wmma::__float_to_tf32(bf0.x[i]);
        for (int i = 0; i < bf1.num_elements; i++)
            bf1.x[i] = wmma::__float_to_tf32(bf1.x[i]);

        wmma::mma_sync(acc0, af, bf0, acc0);
        wmma::mma_sync(acc1, af, bf1, acc1);
    }

    wmma::store_matrix_sync(cs + n0, acc0, PJ_LD, wmma::mem_row_major);
    wmma::store_matrix_sync(cs + n0 + 16, acc1, PJ_LD, wmma::mem_row_major);
    if (tid < 16) rowsq[tid] = 0.0f;
    __syncthreads();

    int r = tid >> 3;
    int c0 = (tid & 7) * 16;
    float vals[16];
    float sq = 0.0f;
    for (int c = 0; c < 16; c++) {
        float v = cs[r * PJ_LD + c0 + c] + bias[c0 + c];
        v = fmaxf(v, 0.0f);
        vals[c] = v;
        sq += v * v;
    }
    atomicAdd(&rowsq[r], sq);
    __syncthreads();

    float s = rsqrtf(rowsq[r]);
    for (int c = 0; c < 16; c++) {
        float o = vals[c] * s;
        pdst[(size_t)r * MI + c0 + c] = o;
        phdst[(size_t)r * MI + c0 + c] = __float2bfloat16_rn(o);
    }
}

// ============ sim kernel (bf16 wmma): exp(dot/T) row + col sums =============
// CTA: 256 threads = 8 warps (4M x 2N); warp tile 32x64; 128x128 CTA tile,
// K=128 resident. Software-pipelined mainloop: all 4 B fragments batched per
// k-step, next k-step's A fragments prefetched under the mma block.
// Register epilogue (accumulator lane mapping verified by Round-7 probe):
//   x[e] -> row = (lane>>2) + ((e>>1)&1)*8
//           col = (lane&3)*2 + (e&1) + ((e>>2)&1)*8
#define SLD 136            // A/B smem row stride in bf16 elements
#define SIM_SMEM (2*128*SLD*2)   // 69632 bytes

__global__ void __launch_bounds__(256, 2) sim_kernel() {
    extern __shared__ unsigned char dynsm[];
    __nv_bfloat16* As = (__nv_bfloat16*)dynsm;
    __nv_bfloat16* Bs = As + 128 * SLD;
    __shared__ float rowred[128];
    __shared__ float colred[128];

    int tid = threadIdx.x;
    int warp = tid >> 5;
    int lane = tid & 31;
    int wm = warp >> 1;          // 0..3  (rows wm*32)
    int wn = warp & 1;           // 0..1  (cols wn*64)
    int i0 = blockIdx.y * 128;
    int j0 = blockIdx.x * 128;

    const uint4* srcA = (const uint4*)(g_p1h + (size_t)i0 * MI);
    const uint4* srcB = (const uint4*)(g_p2h + (size_t)j0 * MI);
    for (int idx = tid; idx < 2048; idx += 256) {
        int r = idx >> 4;
        int ch = idx & 15;
        *(uint4*)(As + r * SLD + ch * 8) = srcA[idx];
        *(uint4*)(Bs + r * SLD + ch * 8) = srcB[idx];
    }
    if (tid < 128) {
        rowred[tid] = 0.0f;
        colred[tid] = 0.0f;
    }
    __syncthreads();

    wmma::fragment<wmma::accumulator, 16, 16, 16, float> acc[2][4];
    #pragma unroll
    for (int mt = 0; mt < 2; mt++) {
        #pragma unroll
        for (int nt = 0; nt < 4; nt++)
            wmma::fill_fragment(acc[mt][nt], 0.0f);
    }

    const __nv_bfloat16* abase = As + (wm * 32) * SLD;
    const __nv_bfloat16* bbase = Bs + (wn * 64) * SLD;

    wmma::fragment<wmma::matrix_a, 16, 16, 16, __nv_bfloat16,
                   wmma::row_major> af0;
    wmma::fragment<wmma::matrix_a, 16, 16, 16, __nv_bfloat16,
                   wmma::row_major> af1;
    wmma::load_matrix_sync(af0, abase, SLD);
    wmma::load_matrix_sync(af1, abase + 16 * SLD, SLD);

    #pragma unroll
    for (int k = 0; k < 8; k++) {
        // batch all 4 B-fragment loads first (their latency is covered by
        // the 8 mmas below)
        wmma::fragment<wmma::matrix_b, 16, 16, 16, __nv_bfloat16,
                       wmma::col_major> bf[4];
        #pragma unroll
        for (int nt = 0; nt < 4; nt++)
            wmma::load_matrix_sync(bf[nt], bbase + nt * 16 * SLD + k * 16,
                                   SLD);

        // prefetch next k-step's A fragments under the mma block
        wmma::fragment<wmma::matrix_a, 16, 16, 16, __nv_bfloat16,
                       wmma::row_major> nf0;
        wmma::fragment<wmma::matrix_a, 16, 16, 16, __nv_bfloat16,
                       wmma::row_major> nf1;
        if (k < 7) {
            wmma::load_matrix_sync(nf0, abase + (k + 1) * 16, SLD);
            wmma::load_matrix_sync(nf1, abase + 16 * SLD + (k + 1) * 16, SLD);
        }

        #pragma unroll
        for (int nt = 0; nt < 4; nt++) {
            wmma::mma_sync(acc[0][nt], af0, bf[nt], acc[0][nt]);
            wmma::mma_sync(acc[1][nt], af1, bf[nt], acc[1][nt]);
        }

        if (k < 7) {
            af0 = nf0;
            af1 = nf1;
        }
    }

    // ---- register epilogue: exp + row/col sums via shuffles ----
    float cs0[4];
    float cs1[4];
    float cs2[4];
    float cs3[4];
    #pragma unroll
    for (int nt = 0; nt < 4; nt++) {
        cs0[nt] = 0.0f;
        cs1[nt] = 0.0f;
        cs2[nt] = 0.0f;
        cs3[nt] = 0.0f;
    }
    #pragma unroll
    for (int mt = 0; mt < 2; mt++) {
        float rlo = 0.0f;
        float rhi = 0.0f;
        #pragma unroll
        for (int nt = 0; nt < 4; nt++) {
            float e0 = __expf(2.0f * acc[mt][nt].x[0]);
            float e1 = __expf(2.0f * acc[mt][nt].x[1]);
            float e2 = __expf(2.0f * acc[mt][nt].x[2]);
            float e3 = __expf(2.0f * acc[mt][nt].x[3]);
            float e4 = __expf(2.0f * acc[mt][nt].x[4]);
            float e5 = __expf(2.0f * acc[mt][nt].x[5]);
            float e6 = __expf(2.0f * acc[mt][nt].x[6]);
            float e7 = __expf(2.0f * acc[mt][nt].x[7]);
            rlo += e0 + e1 + e4 + e5;     // row (lane>>2)
            rhi += e2 + e3 + e6 + e7;     // row (lane>>2)+8
            cs0[nt] += e0 + e2;           // col base
            cs1[nt] += e1 + e3;           // col base+1
            cs2[nt] += e4 + e6;           // col base+8
            cs3[nt] += e5 + e7;           // col base+9
        }
        rlo += __shfl_xor_sync(0xffffffffu, rlo, 1);
        rlo += __shfl_xor_sync(0xffffffffu, rlo, 2);
        rhi += __shfl_xor_sync(0xffffffffu, rhi, 1);
        rhi += __shfl_xor_sync(0xffffffffu, rhi, 2);
        if ((lane & 3) == 0) {
            int r = wm * 32 + mt * 16 + (lane >> 2);
            atomicAdd(&rowred[r], rlo);
            atomicAdd(&rowred[r + 8], rhi);
        }
    }
    #pragma unroll
    for (int nt = 0; nt < 4; nt++) {
        float v0 = cs0[nt];
        float v1 = cs1[nt];
        float v2 = cs2[nt];
        float v3 = cs3[nt];
        v0 += __shfl_xor_sync(0xffffffffu, v0, 4);
        v0 += __shfl_xor_sync(0xffffffffu, v0, 8);
        v0 += __shfl_xor_sync(0xffffffffu, v0, 16);
        v1 += __shfl_xor_sync(0xffffffffu, v1, 4);
        v1 += __shfl_xor_sync(0xffffffffu, v1, 8);
        v1 += __shfl_xor_sync(0xffffffffu, v1, 16);
        v2 += __shfl_xor_sync(0xffffffffu, v2, 4);
        v2 += __shfl_xor_sync(0xffffffffu, v2, 8);
        v2 += __shfl_xor_sync(0xffffffffu, v2, 16);
        v3 += __shfl_xor_sync(0xffffffffu, v3, 4);
        v3 += __shfl_xor_sync(0xffffffffu, v3, 8);
        v3 += __shfl_xor_sync(0xffffffffu, v3, 16);
        if (lane < 4) {
            int cb = wn * 64 + nt * 16 + lane * 2;
            atomicAdd(&colred[cb], v0);
            atomicAdd(&colred[cb + 1], v1);
            atomicAdd(&colred[cb + 8], v2);
            atomicAdd(&colred[cb + 9], v3);
        }
    }
    __syncthreads();

    if (tid < 128) {
        atomicAdd(&g_stats[RS1 + i0 + tid], rowred[tid]);
        atomicAdd(&g_stats[RS2 + j0 + tid], colred[tid]);
    }
}

// ---------------- positives: warp per edge, both directions (fp32) ---------
__global__ void pos_kernel(const int* __restrict__ pr, const int* __restrict__ pc) {
    int e = (blockIdx.x * blockDim.x + threadIdx.x) >> 5;
    int lane = threadIdx.x & 31;
    if (e >= NEDGE) return;
    int r = pr[e];
    int c = pc[e];
    const float4* p1r = (const float4*)(g_p1 + (size_t)r * MI);
    const float4* p2r = (const float4*)(g_p2 + (size_t)r * MI);
    const float4* p1c = (const float4*)(g_p1 + (size_t)c * MI);
    const float4* p2c = (const float4*)(g_p2 + (size_t)c * MI);
    float4 a1 = p1r[lane];
    float4 b2 = p2c[lane];
    float4 a2 = p2r[lane];
    float4 b1 = p1c[lane];
    float d1 = a1.x * b2.x + a1.y * b2.y + a1.z * b2.z + a1.w * b2.w;
    float d2 = a2.x * b1.x + a2.y * b1.y + a2.z * b1.z + a2.w * b1.w;
    for (int o = 16; o > 0; o >>= 1) {
        d1 += __shfl_down_sync(0xffffffffu, d1, o);
        d2 += __shfl_down_sync(0xffffffffu, d2, o);
    }
    if (lane == 0) {
        float s1 = 2.0f * d1;
        float s2 = 2.0f * d2;
        atomicAdd(&g_stats[SP1 + r], s1);
        atomicAdd(&g_stats[PS1 + r], __expf(s1));
        atomicAdd(&g_stats[SP2 + r], s2);
        atomicAdd(&g_stats[PS2 + r], __expf(s2));
    }
}

// ---------------- final loss reduction ----------------
__global__ void loss_kernel(float* out) {
    float acc = 0.f;
    const float invcnt = 0.25f;   // exactly 4 positives per row by construction
    for (int i = threadIdx.x; i < N; i += blockDim.x) {
        float per1 = g_stats[SP1 + i] * invcnt
                   - __logf(g_stats[RS1 + i] - g_stats[PS1 + i]);
        float per2 = g_stats[SP2 + i] * invcnt
                   - __logf(g_stats[RS2 + i] - g_stats[PS2 + i]);
        acc += per1 + per2;
    }
    __shared__ float red[32];
    for (int o = 16; o > 0; o >>= 1)
        acc += __shfl_down_sync(0xffffffffu, acc, o);
    if ((threadIdx.x & 31) == 0) red[threadIdx.x >> 5] = acc;
    __syncthreads();
    if (threadIdx.x == 0) {
        float t = 0.f;
        int nw = blockDim.x >> 5;
        for (int w = 0; w < nw; w++) t += red[w];
        out[0] = -0.5f * t / (float)N;
    }
}

// ---------------- launch ----------------
extern "C" void kernel_launch(void* const* d_in, const int* in_sizes, int n_in,
                              void* d_out, int out_size) {
    const float* h1 = (const float*)d_in[0];
    const float* h2 = (const float*)d_in[1];
    const float* W  = (const float*)d_in[2];
    const float* b  = (const float*)d_in[3];
    const int*   pr = (const int*)d_in[4];
    const int*   pc = (const int*)d_in[5];
    float* out = (float*)d_out;

    proj_kernel<<<(2 * N) / 16, 128>>>(h1, h2, W, b);
    pos_kernel<<<(NEDGE * 32) / 256, 256>>>(pr, pc);
    nop_kernel<<<1, 32>>>();

    cudaFuncSetAttribute(sim_kernel,
                         cudaFuncAttributeMaxDynamicSharedMemorySize, SIM_SMEM);
    dim3 simgrid(N / 128, N / 128);
    sim_kernel<<<simgrid, 256, SIM_SMEM>>>();

    loss_kernel<<<1, 1024>>>(out);
}